// round 3
// baseline (speedup 1.0000x reference)
#include <cuda_runtime.h>

// Problem constants
#define NPTS 16384
#define KNN  16
#define HDIM 64
#define CDIM 10

// Spatial grid
#define GRID  48
#define NCELL (GRID * GRID * GRID)      // 110592
#define BMIN  (-6.4f)
#define CELLH (12.8f / 48.0f)
#define INVH  (48.0f / 12.8f)

#define FINF  __int_as_float(0x7f800000)
#define FNINF __int_as_float(0xff800000)

// ---- scratch (__device__ globals; zero-initialized at load) ----
__device__ float4 g_pts[NPTS];
__device__ int    g_pcell[NPTS];
__device__ int    g_cnt[NCELL];      // zeroed by k_scan each run (invariant)
__device__ int    g_off[NCELL + 1];
__device__ int    g_cur[NCELL];
__device__ float4 g_spts[NPTS];
__device__ int    g_idx[NPTS * KNN];
__device__ float  g_A1[NPTS * HDIM];
__device__ float  g_B1[NPTS * HDIM];
__device__ float  g_h1[NPTS * HDIM];
__device__ float  g_A2[NPTS * HDIM];
__device__ float  g_B2[NPTS * HDIM];
__device__ int    g_gmax[HDIM];      // zeroed by k_out each run (invariant)

__device__ __forceinline__ int cell_of(float v) {
    int c = (int)floorf((v - BMIN) * INVH);
    return min(max(c, 0), GRID - 1);
}

// 16-deep predicated sorted insert (ascending; dist[15] is worst)
#define INSERT(DV, JV)                                              \
    {                                                               \
        float _d = (DV); int _j = (JV);                             \
        _Pragma("unroll")                                           \
        for (int _s = 0; _s < KNN; ++_s) {                          \
            bool _c = _d < dist[_s];                                \
            float _td = dist[_s]; int _ti = idxr[_s];               \
            dist[_s] = _c ? _d : _td;                               \
            idxr[_s] = _c ? _j : _ti;                               \
            _d = _c ? _td : _d;                                     \
            _j = _c ? _ti : _j;                                     \
        }                                                           \
    }

#define SCAN_RANGE(S0, S1)                                          \
    for (int j = (S0) + r; j < (S1); j += 4) {                      \
        float4 cd = g_spts[j];                                      \
        float d = fmaf(ax, cd.x,                                    \
                  fmaf(ay, cd.y,                                    \
                  fmaf(az, cd.z, cd.w + pw)));                      \
        if (d < dist[KNN - 1]) INSERT(d, j)                         \
    }

// ---------------------------------------------------------------------------
// K1: pack points, assign cells, histogram (g_cnt starts zero each run)
__global__ void k_prep(const float* __restrict__ pos) {
    int i = blockIdx.x * blockDim.x + threadIdx.x;
    if (i >= NPTS) return;
    float x = pos[i * 3 + 0];
    float y = pos[i * 3 + 1];
    float z = pos[i * 3 + 2];
    g_pts[i] = make_float4(x, y, z, fmaf(z, z, fmaf(y, y, x * x)));
    int c = (cell_of(z) * GRID + cell_of(y)) * GRID + cell_of(x);
    g_pcell[i] = c;
    atomicAdd(&g_cnt[c], 1);
}

// K2: single-block exclusive scan over NCELL cells; also re-zeroes g_cnt.
__global__ __launch_bounds__(1024) void k_scan() {
    __shared__ int s[1024];
    const int CPT = NCELL / 1024;  // 108
    int t = threadIdx.x;
    int base = t * CPT;
    int sum = 0;
    for (int k = 0; k < CPT; ++k) sum += g_cnt[base + k];
    s[t] = sum;
    __syncthreads();
    for (int off = 1; off < 1024; off <<= 1) {
        int v = (t >= off) ? s[t - off] : 0;
        __syncthreads();
        s[t] += v;
        __syncthreads();
    }
    int run = s[t] - sum;
    for (int k = 0; k < CPT; ++k) {
        int v = g_cnt[base + k];
        g_off[base + k] = run;
        g_cur[base + k] = run;
        g_cnt[base + k] = 0;        // restore invariant for next run
        run += v;
    }
    if (t == 1023) g_off[NCELL] = NPTS;
}

// K3: scatter into cell-sorted order
__global__ void k_scatter() {
    int i = blockIdx.x * blockDim.x + threadIdx.x;
    if (i >= NPTS) return;
    int c = g_pcell[i];
    int slot = atomicAdd(&g_cur[c], 1);
    g_spts[slot] = g_pts[i];
}

// ---------------------------------------------------------------------------
// K4: exact kNN, 4 lanes per query, row-contiguous segment scans,
// expanding-box with exact stop bound (unscanned cells >= m*h away).
__global__ __launch_bounds__(256) void k_knng() {
    int t = blockIdx.x * 256 + threadIdx.x;
    int slot = t >> 2;
    int r = t & 3;
    float4 p = g_spts[slot];
    float pw = p.w;
    float ax = -2.0f * p.x, ay = -2.0f * p.y, az = -2.0f * p.z;
    int cx = cell_of(p.x), cy = cell_of(p.y), cz = cell_of(p.z);

    float dist[KNN];
    int   idxr[KNN];
#pragma unroll
    for (int s = 0; s < KNN; ++s) { dist[s] = FINF; idxr[s] = 0; }

    for (int m = 1; m < GRID; ++m) {
        int zlo = max(cz - m, 0), zhi = min(cz + m, GRID - 1);
        int ylo = max(cy - m, 0), yhi = min(cy + m, GRID - 1);
        int xlo = max(cx - m, 0), xhi = min(cx + m, GRID - 1);
        for (int z = zlo; z <= zhi; ++z) {
            int adz = abs(z - cz);
            int rowz = z * GRID;
            for (int y = ylo; y <= yhi; ++y) {
                bool full = (m == 1) || (max(adz, abs(y - cy)) == m);
                int rowbase = (rowz + y) * GRID;
                if (full) {
                    int c0 = rowbase + xlo;
                    int s0 = g_off[c0], s1 = g_off[c0 + (xhi - xlo + 1)];
                    SCAN_RANGE(s0, s1)
                } else {
                    if (cx - m >= 0) {
                        int c0 = rowbase + cx - m;
                        int s0 = g_off[c0], s1 = g_off[c0 + 1];
                        SCAN_RANGE(s0, s1)
                    }
                    if (cx + m < GRID) {
                        int c0 = rowbase + cx + m;
                        int s0 = g_off[c0], s1 = g_off[c0 + 1];
                        SCAN_RANGE(s0, s1)
                    }
                }
            }
        }
        float bnd = (float)m * CELLH;
        if (dist[KNN - 1] <= bnd * bnd) break;
    }

    // exact 4-way merge within the quad via shfl tree
#pragma unroll
    for (int e = 0; e < KNN; ++e) {
        float dd = __shfl_xor_sync(0xFFFFFFFFu, dist[e], 1);
        int   ji = __shfl_xor_sync(0xFFFFFFFFu, idxr[e], 1);
        if (((r & 1) == 0) && dd < dist[KNN - 1]) INSERT(dd, ji)
    }
#pragma unroll
    for (int e = 0; e < KNN; ++e) {
        float dd = __shfl_xor_sync(0xFFFFFFFFu, dist[e], 2);
        int   ji = __shfl_xor_sync(0xFFFFFFFFu, idxr[e], 2);
        if ((r == 0) && dd < dist[KNN - 1]) INSERT(dd, ji)
    }
    if (r == 0) {
        int off = slot * KNN;
#pragma unroll
        for (int s = 0; s < KNN; ++s) g_idx[off + s] = idxr[s];
    }
}

// ---------------------------------------------------------------------------
// K5: layer-1 projections. A1 = x@(Wa-Wb)+b1, B1 = x@Wb (coalesced float4)
__global__ __launch_bounds__(256) void k_feat1(const float* __restrict__ W1,
                                               const float* __restrict__ b1) {
    __shared__ float sW[6 * HDIM];
    __shared__ float sb[HDIM];
    int tid = threadIdx.x;
    for (int e = tid; e < 6 * HDIM; e += 256) sW[e] = W1[e];
    if (tid < HDIM) sb[tid] = b1[tid];
    __syncthreads();
    int ty = tid >> 4, q = tid & 15;
    int i = blockIdx.x * 16 + ty;
    float4 p = g_spts[i];
    float4 u, v;
    float* up = &u.x; float* vp = &v.x;
#pragma unroll
    for (int e = 0; e < 4; ++e) {
        int h = q * 4 + e;
        float wa0 = sW[0 * HDIM + h], wa1 = sW[1 * HDIM + h], wa2 = sW[2 * HDIM + h];
        float wb0 = sW[3 * HDIM + h], wb1 = sW[4 * HDIM + h], wb2 = sW[5 * HDIM + h];
        vp[e] = fmaf(p.x, wb0, fmaf(p.y, wb1, p.z * wb2));
        up[e] = fmaf(p.x, wa0 - wb0, fmaf(p.y, wa1 - wb1, p.z * (wa2 - wb2))) + sb[h];
    }
    reinterpret_cast<float4*>(g_A1)[i * 16 + q] = u;
    reinterpret_cast<float4*>(g_B1)[i * 16 + q] = v;
}

// ---------------------------------------------------------------------------
// K6: h1 = relu(A1 + max_k B1[idx])
__global__ __launch_bounds__(256) void k_gmax1() {
    int gt = blockIdx.x * 256 + threadIdx.x;
    int i = gt >> 4, q = gt & 15;
    const int4* row = reinterpret_cast<const int4*>(g_idx + i * KNN);
    float4 m = make_float4(FNINF, FNINF, FNINF, FNINF);
#pragma unroll
    for (int k4 = 0; k4 < 4; ++k4) {
        int4 jj = __ldg(row + k4);
        int js[4] = {jj.x, jj.y, jj.z, jj.w};
#pragma unroll
        for (int e = 0; e < 4; ++e) {
            float4 v = reinterpret_cast<const float4*>(g_B1)[js[e] * 16 + q];
            m.x = fmaxf(m.x, v.x); m.y = fmaxf(m.y, v.y);
            m.z = fmaxf(m.z, v.z); m.w = fmaxf(m.w, v.w);
        }
    }
    float4 a = reinterpret_cast<const float4*>(g_A1)[i * 16 + q];
    float4 o;
    o.x = fmaxf(a.x + m.x, 0.0f); o.y = fmaxf(a.y + m.y, 0.0f);
    o.z = fmaxf(a.z + m.z, 0.0f); o.w = fmaxf(a.w + m.w, 0.0f);
    reinterpret_cast<float4*>(g_h1)[i * 16 + q] = o;
}

// ---------------------------------------------------------------------------
// K7: layer-2 projections, register-tiled 4 rows/thread.
// A2 = h1@(W2a-W2b)+b2, B2 = h1@W2b. Block: 64 rows x 16 quads.
__global__ __launch_bounds__(256) void k_feat2(const float* __restrict__ W2,
                                               const float* __restrict__ b2) {
    __shared__ float sWu[HDIM * HDIM];   // 16 KB
    __shared__ float sWv[HDIM * HDIM];   // 16 KB
    __shared__ float sX[64 * HDIM];      // 16 KB
    int tid = threadIdx.x;
    for (int e = tid; e < HDIM * HDIM; e += 256) {
        int j = e >> 6, h = e & 63;
        float wb = W2[(j + HDIM) * HDIM + h];
        sWv[e] = wb;
        sWu[e] = W2[j * HDIM + h] - wb;
    }
    for (int e = tid; e < 64 * 16; e += 256)
        reinterpret_cast<float4*>(sX)[e] =
            reinterpret_cast<const float4*>(g_h1)[blockIdx.x * 1024 + e];
    __syncthreads();

    int ty = tid >> 4, q = tid & 15;     // ty: 0..15 -> rows ty*4..ty*4+3
    float4 au[4], av[4];
#pragma unroll
    for (int k = 0; k < 4; ++k) {
        au[k] = make_float4(0.f, 0.f, 0.f, 0.f);
        av[k] = make_float4(0.f, 0.f, 0.f, 0.f);
    }
#pragma unroll 4
    for (int j = 0; j < HDIM; ++j) {
        float4 wu = reinterpret_cast<const float4*>(sWu)[j * 16 + q];
        float4 wv = reinterpret_cast<const float4*>(sWv)[j * 16 + q];
#pragma unroll
        for (int k = 0; k < 4; ++k) {
            float xj = sX[(ty * 4 + k) * HDIM + j];
            au[k].x = fmaf(xj, wu.x, au[k].x); au[k].y = fmaf(xj, wu.y, au[k].y);
            au[k].z = fmaf(xj, wu.z, au[k].z); au[k].w = fmaf(xj, wu.w, au[k].w);
            av[k].x = fmaf(xj, wv.x, av[k].x); av[k].y = fmaf(xj, wv.y, av[k].y);
            av[k].z = fmaf(xj, wv.z, av[k].z); av[k].w = fmaf(xj, wv.w, av[k].w);
        }
    }
    float4 bb = reinterpret_cast<const float4*>(b2)[q];
#pragma unroll
    for (int k = 0; k < 4; ++k) {
        int i = blockIdx.x * 64 + ty * 4 + k;
        au[k].x += bb.x; au[k].y += bb.y; au[k].z += bb.z; au[k].w += bb.w;
        reinterpret_cast<float4*>(g_A2)[i * 16 + q] = au[k];
        reinterpret_cast<float4*>(g_B2)[i * 16 + q] = av[k];
    }
}

// ---------------------------------------------------------------------------
// K8: h2 = relu(A2 + max_k B2[idx]) folded into global max reduce
__global__ __launch_bounds__(256) void k_gmax2() {
    __shared__ int sg[HDIM];
    if (threadIdx.x < HDIM) sg[threadIdx.x] = 0;
    __syncthreads();
    int gt = blockIdx.x * 256 + threadIdx.x;
    int i = gt >> 4, q = gt & 15;
    const int4* row = reinterpret_cast<const int4*>(g_idx + i * KNN);
    float4 m = make_float4(FNINF, FNINF, FNINF, FNINF);
#pragma unroll
    for (int k4 = 0; k4 < 4; ++k4) {
        int4 jj = __ldg(row + k4);
        int js[4] = {jj.x, jj.y, jj.z, jj.w};
#pragma unroll
        for (int e = 0; e < 4; ++e) {
            float4 v = reinterpret_cast<const float4*>(g_B2)[js[e] * 16 + q];
            m.x = fmaxf(m.x, v.x); m.y = fmaxf(m.y, v.y);
            m.z = fmaxf(m.z, v.z); m.w = fmaxf(m.w, v.w);
        }
    }
    float4 a = reinterpret_cast<const float4*>(g_A2)[i * 16 + q];
    float4 o;
    o.x = fmaxf(a.x + m.x, 0.0f); o.y = fmaxf(a.y + m.y, 0.0f);
    o.z = fmaxf(a.z + m.z, 0.0f); o.w = fmaxf(a.w + m.w, 0.0f);
    atomicMax(&sg[q * 4 + 0], __float_as_int(o.x));
    atomicMax(&sg[q * 4 + 1], __float_as_int(o.y));
    atomicMax(&sg[q * 4 + 2], __float_as_int(o.z));
    atomicMax(&sg[q * 4 + 3], __float_as_int(o.w));
    __syncthreads();
    if (threadIdx.x < HDIM) atomicMax(&g_gmax[threadIdx.x], sg[threadIdx.x]);
}

// ---------------------------------------------------------------------------
// K9: out = g @ Wc + bc ; then re-zero g_gmax for next run
__global__ void k_out(const float* __restrict__ Wc, const float* __restrict__ bc,
                      float* __restrict__ out) {
    int c = threadIdx.x;
    if (c < CDIM) {
        float acc = bc[c];
#pragma unroll
        for (int h = 0; h < HDIM; ++h)
            acc = fmaf(__int_as_float(g_gmax[h]), Wc[h * CDIM + c], acc);
        out[c] = acc;
    }
    __syncthreads();
    if (c < HDIM) g_gmax[c] = 0;   // restore invariant
}

// ---------------------------------------------------------------------------
extern "C" void kernel_launch(void* const* d_in, const int* in_sizes, int n_in,
                              void* d_out, int out_size) {
    const float* pos = (const float*)d_in[0];
    // d_in[1] = batch (all zeros, num_segments=1) -> unused
    const float* W1 = (const float*)d_in[2];
    const float* b1 = (const float*)d_in[3];
    const float* W2 = (const float*)d_in[4];
    const float* b2 = (const float*)d_in[5];
    const float* Wc = (const float*)d_in[6];
    const float* bc = (const float*)d_in[7];
    float* out = (float*)d_out;

    k_prep<<<NPTS / 256, 256>>>(pos);
    k_scan<<<1, 1024>>>();
    k_scatter<<<NPTS / 256, 256>>>();
    k_knng<<<NPTS * 4 / 256, 256>>>();
    k_feat1<<<NPTS / 16, 256>>>(W1, b1);
    k_gmax1<<<NPTS * 16 / 256, 256>>>();
    k_feat2<<<NPTS / 64, 256>>>(W2, b2);
    k_gmax2<<<NPTS * 16 / 256, 256>>>();
    k_out<<<1, 64>>>(Wc, bc, out);
}

// round 4
// speedup vs baseline: 2.0339x; 2.0339x over previous
#include <cuda_runtime.h>

// Problem constants
#define NPTS 16384
#define KNN  16
#define HDIM 64
#define CDIM 10

// Spatial grid: h=0.2 over [-4.8, 4.8]^3
#define GRID  48
#define NCELL (GRID * GRID * GRID)      // 110592
#define BMIN  (-4.8f)
#define CELLH 0.2f
#define INVH  5.0f

// scan decomposition: 108 blocks x 256 threads x 4 cells (one int4)
#define SCAN_BLKS (NCELL / (256 * 4))   // 108

#define FINF  __int_as_float(0x7f800000)
#define FNINF __int_as_float(0xff800000)

// ---- scratch (__device__ globals; zero-initialized at load) ----
__device__ float4 g_pts[NPTS];
__device__ int    g_pcell[NPTS];
__device__ int    g_cnt[NCELL];      // re-zeroed by k_scan3 each run (invariant)
__device__ int    g_off[NCELL + 4];
__device__ int    g_cur[NCELL];
__device__ int    g_bsum[128];
__device__ int    g_bpre[128];
__device__ float4 g_spts[NPTS];
__device__ int    g_idx[NPTS * KNN];
__device__ float  g_A1[NPTS * HDIM];
__device__ float  g_B1[NPTS * HDIM];
__device__ float  g_h1[NPTS * HDIM];
__device__ float  g_A2[NPTS * HDIM];
__device__ float  g_B2[NPTS * HDIM];
__device__ int    g_gmax[HDIM];      // re-zeroed by k_out each run (invariant)

__device__ __forceinline__ int cell_of(float v) {
    int c = (int)floorf((v - BMIN) * INVH);
    return min(max(c, 0), GRID - 1);
}

// ---------------------------------------------------------------------------
// K1: pack points, assign cells, histogram
__global__ void k_prep(const float* __restrict__ pos) {
    int i = blockIdx.x * blockDim.x + threadIdx.x;
    if (i >= NPTS) return;
    float x = pos[i * 3 + 0];
    float y = pos[i * 3 + 1];
    float z = pos[i * 3 + 2];
    g_pts[i] = make_float4(x, y, z, fmaf(z, z, fmaf(y, y, x * x)));
    int c = (cell_of(z) * GRID + cell_of(y)) * GRID + cell_of(x);
    g_pcell[i] = c;
    atomicAdd(&g_cnt[c], 1);
}

// K2a: per-block sums of 1024-cell chunks
__global__ __launch_bounds__(256) void k_scan1() {
    __shared__ int s[256];
    int t = threadIdx.x;
    int4 c = reinterpret_cast<const int4*>(g_cnt)[blockIdx.x * 256 + t];
    s[t] = c.x + c.y + c.z + c.w;
    __syncthreads();
    for (int off = 128; off > 0; off >>= 1) {
        if (t < off) s[t] += s[t + off];
        __syncthreads();
    }
    if (t == 0) g_bsum[blockIdx.x] = s[0];
}

// K2b: exclusive scan of SCAN_BLKS block sums (single small block)
__global__ __launch_bounds__(128) void k_scan2() {
    __shared__ int s[128];
    int t = threadIdx.x;
    int v = (t < SCAN_BLKS) ? g_bsum[t] : 0;
    s[t] = v;
    __syncthreads();
    for (int off = 1; off < 128; off <<= 1) {
        int u = (t >= off) ? s[t - off] : 0;
        __syncthreads();
        s[t] += u;
        __syncthreads();
    }
    g_bpre[t] = s[t] - v;   // exclusive
}

// K2c: expand to per-cell offsets; re-zero g_cnt
__global__ __launch_bounds__(256) void k_scan3() {
    __shared__ int s[256];
    int t = threadIdx.x;
    int gid = blockIdx.x * 256 + t;
    int4 c = reinterpret_cast<const int4*>(g_cnt)[gid];
    int sum = c.x + c.y + c.z + c.w;
    s[t] = sum;
    __syncthreads();
    for (int off = 1; off < 256; off <<= 1) {
        int u = (t >= off) ? s[t - off] : 0;
        __syncthreads();
        s[t] += u;
        __syncthreads();
    }
    int base = g_bpre[blockIdx.x] + s[t] - sum;
    int4 o = make_int4(base, base + c.x, base + c.x + c.y, base + c.x + c.y + c.z);
    reinterpret_cast<int4*>(g_off)[gid] = o;
    reinterpret_cast<int4*>(g_cur)[gid] = o;
    reinterpret_cast<int4*>(g_cnt)[gid] = make_int4(0, 0, 0, 0);
    if (gid == NCELL / 4 - 1) g_off[NCELL] = NPTS;
}

// K3: scatter into cell-sorted order
__global__ void k_scatter() {
    int i = blockIdx.x * blockDim.x + threadIdx.x;
    if (i >= NPTS) return;
    int c = g_pcell[i];
    int slot = atomicAdd(&g_cur[c], 1);
    g_spts[slot] = g_pts[i];
}

// ---------------------------------------------------------------------------
// K4: exact kNN, ONE WARP PER QUERY.
// Top-16 kept sorted & distributed across lanes 0..15 (lane l = l-th best).
// Warp scans candidate segments coalesced; ballot filters vs warp-uniform
// kth; each survivor inserted with a 2-shfl shift-insert (non-divergent).
// Expanding box, exact face-distance stop bound.
__global__ __launch_bounds__(256) void k_knng() {
    const unsigned FULL = 0xFFFFFFFFu;
    int warp = (blockIdx.x * 256 + threadIdx.x) >> 5;
    int lane = threadIdx.x & 31;
    float4 p = g_spts[warp];
    float pw = p.w;
    float ax = -2.0f * p.x, ay = -2.0f * p.y, az = -2.0f * p.z;
    int cx = cell_of(p.x), cy = cell_of(p.y), cz = cell_of(p.z);

    float bd = FINF;   // lane l (<16): l-th smallest distance so far
    int   bj = 0;      // its index
    float kth = FINF;  // warp-uniform 16th best

    for (int m = 1; m < GRID; ++m) {
        int zlo = max(cz - m, 0), zhi = min(cz + m, GRID - 1);
        int ylo = max(cy - m, 0), yhi = min(cy + m, GRID - 1);
        int xlo = max(cx - m, 0), xhi = min(cx + m, GRID - 1);
        for (int z = zlo; z <= zhi; ++z) {
            int adz = abs(z - cz);
            for (int y = ylo; y <= yhi; ++y) {
                bool fullrow = (m == 1) || (max(adz, abs(y - cy)) == m);
                int rowbase = (z * GRID + y) * GRID;
                int s0, s1, s0b = 0, s1b = 0;
                if (fullrow) {
                    s0 = g_off[rowbase + xlo];
                    s1 = g_off[rowbase + xhi + 1];
                } else {
                    if (cx - m >= 0) {
                        s0 = g_off[rowbase + cx - m];
                        s1 = g_off[rowbase + cx - m + 1];
                    } else { s0 = 0; s1 = 0; }
                    if (cx + m < GRID) {
                        s0b = g_off[rowbase + cx + m];
                        s1b = g_off[rowbase + cx + m + 1];
                    }
                }
                for (int pass = 0; pass < 2; ++pass) {
                    int a = pass ? s0b : s0;
                    int b = pass ? s1b : s1;
                    for (int base = a; base < b; base += 32) {
                        int j = base + lane;
                        float d = FINF;
                        if (j < b) {
                            float4 cd = g_spts[j];
                            d = fmaf(ax, cd.x,
                                fmaf(ay, cd.y,
                                fmaf(az, cd.z, cd.w + pw)));
                        }
                        unsigned msk = __ballot_sync(FULL, d < kth);
                        while (msk) {
                            int src = __ffs(msk) - 1;
                            msk &= msk - 1;
                            float dw = __shfl_sync(FULL, d, src);
                            int   jw = __shfl_sync(FULL, j, src);
                            if (dw < kth) {
                                float pbd = __shfl_up_sync(FULL, bd, 1);
                                int   pbj = __shfl_up_sync(FULL, bj, 1);
                                bool ins  = dw < bd;
                                bool pins = (lane > 0) && (dw < pbd);
                                bd = ins ? (pins ? pbd : dw) : bd;
                                bj = ins ? (pins ? pbj : jw) : bj;
                                kth = __shfl_sync(FULL, bd, KNN - 1);
                            }
                        }
                    }
                    if (fullrow) break;
                }
            }
        }
        // exact stop: distance from p to scanned-box faces (inf at grid edge)
        float b0 = (xlo > 0)        ? (p.x - (BMIN + (float)xlo * CELLH))       : FINF;
        float b1 = (xhi < GRID - 1) ? ((BMIN + (float)(xhi + 1) * CELLH) - p.x) : FINF;
        float b2 = (ylo > 0)        ? (p.y - (BMIN + (float)ylo * CELLH))       : FINF;
        float b3 = (yhi < GRID - 1) ? ((BMIN + (float)(yhi + 1) * CELLH) - p.y) : FINF;
        float b4 = (zlo > 0)        ? (p.z - (BMIN + (float)zlo * CELLH))       : FINF;
        float b5 = (zhi < GRID - 1) ? ((BMIN + (float)(zhi + 1) * CELLH) - p.z) : FINF;
        float bb = fminf(fminf(fminf(b0, b1), fminf(b2, b3)), fminf(b4, b5));
        bb -= 1e-4f;  // fp-exactness slack on face positions
        if (kth <= bb * bb) break;
    }
    if (lane < KNN) g_idx[warp * KNN + lane] = bj;
}

// ---------------------------------------------------------------------------
// K5: layer-1 projections. A1 = x@(Wa-Wb)+b1, B1 = x@Wb (coalesced float4)
__global__ __launch_bounds__(256) void k_feat1(const float* __restrict__ W1,
                                               const float* __restrict__ b1) {
    __shared__ float sW[6 * HDIM];
    __shared__ float sb[HDIM];
    int tid = threadIdx.x;
    for (int e = tid; e < 6 * HDIM; e += 256) sW[e] = W1[e];
    if (tid < HDIM) sb[tid] = b1[tid];
    __syncthreads();
    int ty = tid >> 4, q = tid & 15;
    int i = blockIdx.x * 16 + ty;
    float4 p = g_spts[i];
    float4 u, v;
    float* up = &u.x; float* vp = &v.x;
#pragma unroll
    for (int e = 0; e < 4; ++e) {
        int h = q * 4 + e;
        float wa0 = sW[0 * HDIM + h], wa1 = sW[1 * HDIM + h], wa2 = sW[2 * HDIM + h];
        float wb0 = sW[3 * HDIM + h], wb1 = sW[4 * HDIM + h], wb2 = sW[5 * HDIM + h];
        vp[e] = fmaf(p.x, wb0, fmaf(p.y, wb1, p.z * wb2));
        up[e] = fmaf(p.x, wa0 - wb0, fmaf(p.y, wa1 - wb1, p.z * (wa2 - wb2))) + sb[h];
    }
    reinterpret_cast<float4*>(g_A1)[i * 16 + q] = u;
    reinterpret_cast<float4*>(g_B1)[i * 16 + q] = v;
}

// ---------------------------------------------------------------------------
// K6: h1 = relu(A1 + max_k B1[idx])
__global__ __launch_bounds__(256) void k_gmax1() {
    int gt = blockIdx.x * 256 + threadIdx.x;
    int i = gt >> 4, q = gt & 15;
    const int4* row = reinterpret_cast<const int4*>(g_idx + i * KNN);
    float4 m = make_float4(FNINF, FNINF, FNINF, FNINF);
#pragma unroll
    for (int k4 = 0; k4 < 4; ++k4) {
        int4 jj = __ldg(row + k4);
        int js[4] = {jj.x, jj.y, jj.z, jj.w};
#pragma unroll
        for (int e = 0; e < 4; ++e) {
            float4 v = reinterpret_cast<const float4*>(g_B1)[js[e] * 16 + q];
            m.x = fmaxf(m.x, v.x); m.y = fmaxf(m.y, v.y);
            m.z = fmaxf(m.z, v.z); m.w = fmaxf(m.w, v.w);
        }
    }
    float4 a = reinterpret_cast<const float4*>(g_A1)[i * 16 + q];
    float4 o;
    o.x = fmaxf(a.x + m.x, 0.0f); o.y = fmaxf(a.y + m.y, 0.0f);
    o.z = fmaxf(a.z + m.z, 0.0f); o.w = fmaxf(a.w + m.w, 0.0f);
    reinterpret_cast<float4*>(g_h1)[i * 16 + q] = o;
}

// ---------------------------------------------------------------------------
// K7: layer-2 projections, register-tiled 4 rows/thread.
__global__ __launch_bounds__(256) void k_feat2(const float* __restrict__ W2,
                                               const float* __restrict__ b2) {
    __shared__ float sWu[HDIM * HDIM];
    __shared__ float sWv[HDIM * HDIM];
    __shared__ float sX[64 * HDIM];
    int tid = threadIdx.x;
    for (int e = tid; e < HDIM * HDIM; e += 256) {
        int j = e >> 6, h = e & 63;
        float wb = W2[(j + HDIM) * HDIM + h];
        sWv[e] = wb;
        sWu[e] = W2[j * HDIM + h] - wb;
    }
    for (int e = tid; e < 64 * 16; e += 256)
        reinterpret_cast<float4*>(sX)[e] =
            reinterpret_cast<const float4*>(g_h1)[blockIdx.x * 1024 + e];
    __syncthreads();

    int ty = tid >> 4, q = tid & 15;
    float4 au[4], av[4];
#pragma unroll
    for (int k = 0; k < 4; ++k) {
        au[k] = make_float4(0.f, 0.f, 0.f, 0.f);
        av[k] = make_float4(0.f, 0.f, 0.f, 0.f);
    }
#pragma unroll 4
    for (int j = 0; j < HDIM; ++j) {
        float4 wu = reinterpret_cast<const float4*>(sWu)[j * 16 + q];
        float4 wv = reinterpret_cast<const float4*>(sWv)[j * 16 + q];
#pragma unroll
        for (int k = 0; k < 4; ++k) {
            float xj = sX[(ty * 4 + k) * HDIM + j];
            au[k].x = fmaf(xj, wu.x, au[k].x); au[k].y = fmaf(xj, wu.y, au[k].y);
            au[k].z = fmaf(xj, wu.z, au[k].z); au[k].w = fmaf(xj, wu.w, au[k].w);
            av[k].x = fmaf(xj, wv.x, av[k].x); av[k].y = fmaf(xj, wv.y, av[k].y);
            av[k].z = fmaf(xj, wv.z, av[k].z); av[k].w = fmaf(xj, wv.w, av[k].w);
        }
    }
    float4 bb = reinterpret_cast<const float4*>(b2)[q];
#pragma unroll
    for (int k = 0; k < 4; ++k) {
        int i = blockIdx.x * 64 + ty * 4 + k;
        au[k].x += bb.x; au[k].y += bb.y; au[k].z += bb.z; au[k].w += bb.w;
        reinterpret_cast<float4*>(g_A2)[i * 16 + q] = au[k];
        reinterpret_cast<float4*>(g_B2)[i * 16 + q] = av[k];
    }
}

// ---------------------------------------------------------------------------
// K8: h2 = relu(A2 + max_k B2[idx]) folded into global max reduce
__global__ __launch_bounds__(256) void k_gmax2() {
    __shared__ int sg[HDIM];
    if (threadIdx.x < HDIM) sg[threadIdx.x] = 0;
    __syncthreads();
    int gt = blockIdx.x * 256 + threadIdx.x;
    int i = gt >> 4, q = gt & 15;
    const int4* row = reinterpret_cast<const int4*>(g_idx + i * KNN);
    float4 m = make_float4(FNINF, FNINF, FNINF, FNINF);
#pragma unroll
    for (int k4 = 0; k4 < 4; ++k4) {
        int4 jj = __ldg(row + k4);
        int js[4] = {jj.x, jj.y, jj.z, jj.w};
#pragma unroll
        for (int e = 0; e < 4; ++e) {
            float4 v = reinterpret_cast<const float4*>(g_B2)[js[e] * 16 + q];
            m.x = fmaxf(m.x, v.x); m.y = fmaxf(m.y, v.y);
            m.z = fmaxf(m.z, v.z); m.w = fmaxf(m.w, v.w);
        }
    }
    float4 a = reinterpret_cast<const float4*>(g_A2)[i * 16 + q];
    float4 o;
    o.x = fmaxf(a.x + m.x, 0.0f); o.y = fmaxf(a.y + m.y, 0.0f);
    o.z = fmaxf(a.z + m.z, 0.0f); o.w = fmaxf(a.w + m.w, 0.0f);
    atomicMax(&sg[q * 4 + 0], __float_as_int(o.x));
    atomicMax(&sg[q * 4 + 1], __float_as_int(o.y));
    atomicMax(&sg[q * 4 + 2], __float_as_int(o.z));
    atomicMax(&sg[q * 4 + 3], __float_as_int(o.w));
    __syncthreads();
    if (threadIdx.x < HDIM) atomicMax(&g_gmax[threadIdx.x], sg[threadIdx.x]);
}

// ---------------------------------------------------------------------------
// K9: out = g @ Wc + bc ; then re-zero g_gmax for next run
__global__ void k_out(const float* __restrict__ Wc, const float* __restrict__ bc,
                      float* __restrict__ out) {
    int c = threadIdx.x;
    if (c < CDIM) {
        float acc = bc[c];
#pragma unroll
        for (int h = 0; h < HDIM; ++h)
            acc = fmaf(__int_as_float(g_gmax[h]), Wc[h * CDIM + c], acc);
        out[c] = acc;
    }
    __syncthreads();
    if (c < HDIM) g_gmax[c] = 0;
}

// ---------------------------------------------------------------------------
extern "C" void kernel_launch(void* const* d_in, const int* in_sizes, int n_in,
                              void* d_out, int out_size) {
    const float* pos = (const float*)d_in[0];
    // d_in[1] = batch (all zeros, num_segments=1) -> unused
    const float* W1 = (const float*)d_in[2];
    const float* b1 = (const float*)d_in[3];
    const float* W2 = (const float*)d_in[4];
    const float* b2 = (const float*)d_in[5];
    const float* Wc = (const float*)d_in[6];
    const float* bc = (const float*)d_in[7];
    float* out = (float*)d_out;

    k_prep<<<NPTS / 256, 256>>>(pos);
    k_scan1<<<SCAN_BLKS, 256>>>();
    k_scan2<<<1, 128>>>();
    k_scan3<<<SCAN_BLKS, 256>>>();
    k_scatter<<<NPTS / 256, 256>>>();
    k_knng<<<NPTS * 32 / 256, 256>>>();
    k_feat1<<<NPTS / 16, 256>>>(W1, b1);
    k_gmax1<<<NPTS * 16 / 256, 256>>>();
    k_feat2<<<NPTS / 64, 256>>>(W2, b2);
    k_gmax2<<<NPTS * 16 / 256, 256>>>();
    k_out<<<1, 64>>>(Wc, bc, out);
}

// round 5
// speedup vs baseline: 4.8661x; 2.3925x over previous
#include <cuda_runtime.h>

// Problem constants
#define NPTS 16384
#define KNN  16
#define HDIM 64
#define CDIM 10

// Spatial grid: h=0.3 over [-4.8, 4.8]^3
#define GRID  32
#define NCELL (GRID * GRID * GRID)      // 32768
#define BMIN  (-4.8f)
#define CELLH 0.3f
#define INVH  (1.0f / 0.3f)

// scan decomposition: 32 blocks x 256 threads x 4 cells (one int4)
#define SCAN_BLKS (NCELL / (256 * 4))   // 32

#define FINF  __int_as_float(0x7f800000)
#define FNINF __int_as_float(0xff800000)

// ---- scratch (__device__ globals; zero-initialized at load) ----
__device__ float4 g_pts[NPTS];
__device__ int    g_pcell[NPTS];
__device__ int    g_cnt[NCELL];      // re-zeroed by k_scan3 each run (invariant)
__device__ int    g_off[NCELL + 4];
__device__ int    g_cur[NCELL];
__device__ int    g_bsum[128];
__device__ int    g_bpre[128];
__device__ float4 g_spts[NPTS];
__device__ int    g_idx[NPTS * KNN];
__device__ float  g_A1[NPTS * HDIM];
__device__ float  g_B1[NPTS * HDIM];
__device__ float  g_h1[NPTS * HDIM];
__device__ float  g_A2[NPTS * HDIM];
__device__ float  g_B2[NPTS * HDIM];
__device__ int    g_gmax[HDIM];      // re-zeroed by k_out each run (invariant)

__device__ __forceinline__ int cell_of(float v) {
    int c = (int)floorf((v - BMIN) * INVH);
    return min(max(c, 0), GRID - 1);
}

// ---------------------------------------------------------------------------
// K1: pack points, assign cells, histogram
__global__ void k_prep(const float* __restrict__ pos) {
    int i = blockIdx.x * blockDim.x + threadIdx.x;
    if (i >= NPTS) return;
    float x = pos[i * 3 + 0];
    float y = pos[i * 3 + 1];
    float z = pos[i * 3 + 2];
    g_pts[i] = make_float4(x, y, z, fmaf(z, z, fmaf(y, y, x * x)));
    int c = (cell_of(z) * GRID + cell_of(y)) * GRID + cell_of(x);
    g_pcell[i] = c;
    atomicAdd(&g_cnt[c], 1);
}

// K2a: per-block sums of 1024-cell chunks
__global__ __launch_bounds__(256) void k_scan1() {
    __shared__ int s[256];
    int t = threadIdx.x;
    int4 c = reinterpret_cast<const int4*>(g_cnt)[blockIdx.x * 256 + t];
    s[t] = c.x + c.y + c.z + c.w;
    __syncthreads();
    for (int off = 128; off > 0; off >>= 1) {
        if (t < off) s[t] += s[t + off];
        __syncthreads();
    }
    if (t == 0) g_bsum[blockIdx.x] = s[0];
}

// K2b: exclusive scan of SCAN_BLKS block sums (single small block)
__global__ __launch_bounds__(128) void k_scan2() {
    __shared__ int s[128];
    int t = threadIdx.x;
    int v = (t < SCAN_BLKS) ? g_bsum[t] : 0;
    s[t] = v;
    __syncthreads();
    for (int off = 1; off < 128; off <<= 1) {
        int u = (t >= off) ? s[t - off] : 0;
        __syncthreads();
        s[t] += u;
        __syncthreads();
    }
    g_bpre[t] = s[t] - v;   // exclusive
}

// K2c: expand to per-cell offsets; re-zero g_cnt
__global__ __launch_bounds__(256) void k_scan3() {
    __shared__ int s[256];
    int t = threadIdx.x;
    int gid = blockIdx.x * 256 + t;
    int4 c = reinterpret_cast<const int4*>(g_cnt)[gid];
    int sum = c.x + c.y + c.z + c.w;
    s[t] = sum;
    __syncthreads();
    for (int off = 1; off < 256; off <<= 1) {
        int u = (t >= off) ? s[t - off] : 0;
        __syncthreads();
        s[t] += u;
        __syncthreads();
    }
    int base = g_bpre[blockIdx.x] + s[t] - sum;
    int4 o = make_int4(base, base + c.x, base + c.x + c.y, base + c.x + c.y + c.z);
    reinterpret_cast<int4*>(g_off)[gid] = o;
    reinterpret_cast<int4*>(g_cur)[gid] = o;
    reinterpret_cast<int4*>(g_cnt)[gid] = make_int4(0, 0, 0, 0);
    if (gid == NCELL / 4 - 1) g_off[NCELL] = NPTS;
}

// K3: scatter into cell-sorted order
__global__ void k_scatter() {
    int i = blockIdx.x * blockDim.x + threadIdx.x;
    if (i >= NPTS) return;
    int c = g_pcell[i];
    int slot = atomicAdd(&g_cur[c], 1);
    g_spts[slot] = g_pts[i];
}

// ---------------------------------------------------------------------------
// K4: exact kNN, one warp per query.
// Top-16 sorted & distributed across lanes 0..15. Candidates scanned in
// coalesced 32-wide tiles; ballot filter vs (stale-safe) kth; shift-insert
// per survivor with a single shfl_up chain. Row segment offsets for each
// shell fetched one-row-per-lane in parallel, then replayed via shfl.
#define SCANSEG(A, B)                                                         \
    for (int base = (A); base < (B); base += 32) {                            \
        int j = base + lane;                                                  \
        float d = FINF;                                                       \
        if (j < (B)) {                                                        \
            float4 cd = __ldg(&g_spts[j]);                                    \
            d = fmaf(ax, cd.x, fmaf(ay, cd.y, fmaf(az, cd.z, cd.w + pw)));    \
        }                                                                     \
        unsigned msk = __ballot_sync(FULL, d < kth);                          \
        if (msk) {                                                            \
            do {                                                              \
                int src = __ffs(msk) - 1;                                     \
                msk &= msk - 1;                                               \
                float dw = __shfl_sync(FULL, d, src);                         \
                int   jw = __shfl_sync(FULL, j, src);                         \
                float pbd = __shfl_up_sync(FULL, bd, 1);                      \
                int   pbj = __shfl_up_sync(FULL, bj, 1);                      \
                bool ins  = dw < bd;                                          \
                bool pins = (lane > 0) && (dw < pbd);                         \
                bd = ins ? (pins ? pbd : dw) : bd;                            \
                bj = ins ? (pins ? pbj : jw) : bj;                            \
            } while (msk);                                                    \
            kth = __shfl_sync(FULL, bd, KNN - 1);                             \
        }                                                                     \
    }

__global__ __launch_bounds__(256) void k_knng() {
    const unsigned FULL = 0xFFFFFFFFu;
    int warp = (blockIdx.x * 256 + threadIdx.x) >> 5;
    int lane = threadIdx.x & 31;
    float4 p = g_spts[warp];
    float pw = p.w;
    float ax = -2.0f * p.x, ay = -2.0f * p.y, az = -2.0f * p.z;
    int cx = cell_of(p.x), cy = cell_of(p.y), cz = cell_of(p.z);

    float bd = FINF;   // lane l (<16): l-th smallest distance so far
    int   bj = 0;
    float kth = FINF;  // warp-uniform (possibly slightly stale) 16th best

    for (int m = 1; m < GRID; ++m) {
        int zlo = max(cz - m, 0), zhi = min(cz + m, GRID - 1);
        int ylo = max(cy - m, 0), yhi = min(cy + m, GRID - 1);
        int xlo = max(cx - m, 0), xhi = min(cx + m, GRID - 1);
        int ny = yhi - ylo + 1;
        int nrows = (zhi - zlo + 1) * ny;

        for (int rbase = 0; rbase < nrows; rbase += 32) {
            int rid = rbase + lane;
            int a0 = 0, a1 = 0, b0 = 0, b1 = 0;
            if (rid < nrows) {
                int z = zlo + rid / ny;
                int y = ylo + rid - (rid / ny) * ny;
                int rb = (z * GRID + y) * GRID;
                bool fullrow = (m == 1) || (abs(z - cz) == m) || (abs(y - cy) == m);
                if (fullrow) {
                    a0 = __ldg(&g_off[rb + xlo]);
                    a1 = __ldg(&g_off[rb + xhi + 1]);
                } else {
                    if (cx - m >= 0) {
                        a0 = __ldg(&g_off[rb + cx - m]);
                        a1 = __ldg(&g_off[rb + cx - m + 1]);
                    }
                    if (cx + m < GRID) {
                        b0 = __ldg(&g_off[rb + cx + m]);
                        b1 = __ldg(&g_off[rb + cx + m + 1]);
                    }
                }
            }
            int cnt = min(nrows - rbase, 32);
            for (int r = 0; r < cnt; ++r) {
                int sa0 = __shfl_sync(FULL, a0, r);
                int sa1 = __shfl_sync(FULL, a1, r);
                SCANSEG(sa0, sa1)
                int sb0 = __shfl_sync(FULL, b0, r);
                int sb1 = __shfl_sync(FULL, b1, r);
                SCANSEG(sb0, sb1)
            }
        }

        // exact stop: distance from p to scanned-box faces (inf at grid edge)
        float f0 = (xlo > 0)        ? (p.x - (BMIN + (float)xlo * CELLH))       : FINF;
        float f1 = (xhi < GRID - 1) ? ((BMIN + (float)(xhi + 1) * CELLH) - p.x) : FINF;
        float f2 = (ylo > 0)        ? (p.y - (BMIN + (float)ylo * CELLH))       : FINF;
        float f3 = (yhi < GRID - 1) ? ((BMIN + (float)(yhi + 1) * CELLH) - p.y) : FINF;
        float f4 = (zlo > 0)        ? (p.z - (BMIN + (float)zlo * CELLH))       : FINF;
        float f5 = (zhi < GRID - 1) ? ((BMIN + (float)(zhi + 1) * CELLH) - p.z) : FINF;
        float bb = fminf(fminf(fminf(f0, f1), fminf(f2, f3)), fminf(f4, f5));
        bb -= 1e-4f;  // fp slack on face positions
        if (kth <= bb * bb) break;
    }
    if (lane < KNN) g_idx[warp * KNN + lane] = bj;
}

// ---------------------------------------------------------------------------
// K5: layer-1 projections. A1 = x@(Wa-Wb)+b1, B1 = x@Wb (coalesced float4)
__global__ __launch_bounds__(256) void k_feat1(const float* __restrict__ W1,
                                               const float* __restrict__ b1) {
    __shared__ float sW[6 * HDIM];
    __shared__ float sb[HDIM];
    int tid = threadIdx.x;
    for (int e = tid; e < 6 * HDIM; e += 256) sW[e] = W1[e];
    if (tid < HDIM) sb[tid] = b1[tid];
    __syncthreads();
    int ty = tid >> 4, q = tid & 15;
    int i = blockIdx.x * 16 + ty;
    float4 p = g_spts[i];
    float4 u, v;
    float* up = &u.x; float* vp = &v.x;
#pragma unroll
    for (int e = 0; e < 4; ++e) {
        int h = q * 4 + e;
        float wa0 = sW[0 * HDIM + h], wa1 = sW[1 * HDIM + h], wa2 = sW[2 * HDIM + h];
        float wb0 = sW[3 * HDIM + h], wb1 = sW[4 * HDIM + h], wb2 = sW[5 * HDIM + h];
        vp[e] = fmaf(p.x, wb0, fmaf(p.y, wb1, p.z * wb2));
        up[e] = fmaf(p.x, wa0 - wb0, fmaf(p.y, wa1 - wb1, p.z * (wa2 - wb2))) + sb[h];
    }
    reinterpret_cast<float4*>(g_A1)[i * 16 + q] = u;
    reinterpret_cast<float4*>(g_B1)[i * 16 + q] = v;
}

// ---------------------------------------------------------------------------
// K6: h1 = relu(A1 + max_k B1[idx])
__global__ __launch_bounds__(256) void k_gmax1() {
    int gt = blockIdx.x * 256 + threadIdx.x;
    int i = gt >> 4, q = gt & 15;
    const int4* row = reinterpret_cast<const int4*>(g_idx + i * KNN);
    float4 m = make_float4(FNINF, FNINF, FNINF, FNINF);
#pragma unroll
    for (int k4 = 0; k4 < 4; ++k4) {
        int4 jj = __ldg(row + k4);
        int js[4] = {jj.x, jj.y, jj.z, jj.w};
#pragma unroll
        for (int e = 0; e < 4; ++e) {
            float4 v = reinterpret_cast<const float4*>(g_B1)[js[e] * 16 + q];
            m.x = fmaxf(m.x, v.x); m.y = fmaxf(m.y, v.y);
            m.z = fmaxf(m.z, v.z); m.w = fmaxf(m.w, v.w);
        }
    }
    float4 a = reinterpret_cast<const float4*>(g_A1)[i * 16 + q];
    float4 o;
    o.x = fmaxf(a.x + m.x, 0.0f); o.y = fmaxf(a.y + m.y, 0.0f);
    o.z = fmaxf(a.z + m.z, 0.0f); o.w = fmaxf(a.w + m.w, 0.0f);
    reinterpret_cast<float4*>(g_h1)[i * 16 + q] = o;
}

// ---------------------------------------------------------------------------
// K7: layer-2 projections, register-tiled 4 rows/thread.
__global__ __launch_bounds__(256) void k_feat2(const float* __restrict__ W2,
                                               const float* __restrict__ b2) {
    __shared__ float sWu[HDIM * HDIM];
    __shared__ float sWv[HDIM * HDIM];
    __shared__ float sX[64 * HDIM];
    int tid = threadIdx.x;
    for (int e = tid; e < HDIM * HDIM; e += 256) {
        int j = e >> 6, h = e & 63;
        float wb = W2[(j + HDIM) * HDIM + h];
        sWv[e] = wb;
        sWu[e] = W2[j * HDIM + h] - wb;
    }
    for (int e = tid; e < 64 * 16; e += 256)
        reinterpret_cast<float4*>(sX)[e] =
            reinterpret_cast<const float4*>(g_h1)[blockIdx.x * 1024 + e];
    __syncthreads();

    int ty = tid >> 4, q = tid & 15;
    float4 au[4], av[4];
#pragma unroll
    for (int k = 0; k < 4; ++k) {
        au[k] = make_float4(0.f, 0.f, 0.f, 0.f);
        av[k] = make_float4(0.f, 0.f, 0.f, 0.f);
    }
#pragma unroll 4
    for (int j = 0; j < HDIM; ++j) {
        float4 wu = reinterpret_cast<const float4*>(sWu)[j * 16 + q];
        float4 wv = reinterpret_cast<const float4*>(sWv)[j * 16 + q];
#pragma unroll
        for (int k = 0; k < 4; ++k) {
            float xj = sX[(ty * 4 + k) * HDIM + j];
            au[k].x = fmaf(xj, wu.x, au[k].x); au[k].y = fmaf(xj, wu.y, au[k].y);
            au[k].z = fmaf(xj, wu.z, au[k].z); au[k].w = fmaf(xj, wu.w, au[k].w);
            av[k].x = fmaf(xj, wv.x, av[k].x); av[k].y = fmaf(xj, wv.y, av[k].y);
            av[k].z = fmaf(xj, wv.z, av[k].z); av[k].w = fmaf(xj, wv.w, av[k].w);
        }
    }
    float4 bb = reinterpret_cast<const float4*>(b2)[q];
#pragma unroll
    for (int k = 0; k < 4; ++k) {
        int i = blockIdx.x * 64 + ty * 4 + k;
        au[k].x += bb.x; au[k].y += bb.y; au[k].z += bb.z; au[k].w += bb.w;
        reinterpret_cast<float4*>(g_A2)[i * 16 + q] = au[k];
        reinterpret_cast<float4*>(g_B2)[i * 16 + q] = av[k];
    }
}

// ---------------------------------------------------------------------------
// K8: h2 = relu(A2 + max_k B2[idx]) folded into global max reduce
__global__ __launch_bounds__(256) void k_gmax2() {
    __shared__ int sg[HDIM];
    if (threadIdx.x < HDIM) sg[threadIdx.x] = 0;
    __syncthreads();
    int gt = blockIdx.x * 256 + threadIdx.x;
    int i = gt >> 4, q = gt & 15;
    const int4* row = reinterpret_cast<const int4*>(g_idx + i * KNN);
    float4 m = make_float4(FNINF, FNINF, FNINF, FNINF);
#pragma unroll
    for (int k4 = 0; k4 < 4; ++k4) {
        int4 jj = __ldg(row + k4);
        int js[4] = {jj.x, jj.y, jj.z, jj.w};
#pragma unroll
        for (int e = 0; e < 4; ++e) {
            float4 v = reinterpret_cast<const float4*>(g_B2)[js[e] * 16 + q];
            m.x = fmaxf(m.x, v.x); m.y = fmaxf(m.y, v.y);
            m.z = fmaxf(m.z, v.z); m.w = fmaxf(m.w, v.w);
        }
    }
    float4 a = reinterpret_cast<const float4*>(g_A2)[i * 16 + q];
    float4 o;
    o.x = fmaxf(a.x + m.x, 0.0f); o.y = fmaxf(a.y + m.y, 0.0f);
    o.z = fmaxf(a.z + m.z, 0.0f); o.w = fmaxf(a.w + m.w, 0.0f);
    atomicMax(&sg[q * 4 + 0], __float_as_int(o.x));
    atomicMax(&sg[q * 4 + 1], __float_as_int(o.y));
    atomicMax(&sg[q * 4 + 2], __float_as_int(o.z));
    atomicMax(&sg[q * 4 + 3], __float_as_int(o.w));
    __syncthreads();
    if (threadIdx.x < HDIM) atomicMax(&g_gmax[threadIdx.x], sg[threadIdx.x]);
}

// ---------------------------------------------------------------------------
// K9: out = g @ Wc + bc ; then re-zero g_gmax for next run
__global__ void k_out(const float* __restrict__ Wc, const float* __restrict__ bc,
                      float* __restrict__ out) {
    int c = threadIdx.x;
    if (c < CDIM) {
        float acc = bc[c];
#pragma unroll
        for (int h = 0; h < HDIM; ++h)
            acc = fmaf(__int_as_float(g_gmax[h]), Wc[h * CDIM + c], acc);
        out[c] = acc;
    }
    __syncthreads();
    if (c < HDIM) g_gmax[c] = 0;
}

// ---------------------------------------------------------------------------
extern "C" void kernel_launch(void* const* d_in, const int* in_sizes, int n_in,
                              void* d_out, int out_size) {
    const float* pos = (const float*)d_in[0];
    // d_in[1] = batch (all zeros, num_segments=1) -> unused
    const float* W1 = (const float*)d_in[2];
    const float* b1 = (const float*)d_in[3];
    const float* W2 = (const float*)d_in[4];
    const float* b2 = (const float*)d_in[5];
    const float* Wc = (const float*)d_in[6];
    const float* bc = (const float*)d_in[7];
    float* out = (float*)d_out;

    k_prep<<<NPTS / 256, 256>>>(pos);
    k_scan1<<<SCAN_BLKS, 256>>>();
    k_scan2<<<1, 128>>>();
    k_scan3<<<SCAN_BLKS, 256>>>();
    k_scatter<<<NPTS / 256, 256>>>();
    k_knng<<<NPTS * 32 / 256, 256>>>();
    k_feat1<<<NPTS / 16, 256>>>(W1, b1);
    k_gmax1<<<NPTS * 16 / 256, 256>>>();
    k_feat2<<<NPTS / 64, 256>>>(W2, b2);
    k_gmax2<<<NPTS * 16 / 256, 256>>>();
    k_out<<<1, 64>>>(Wc, bc, out);
}